// round 3
// baseline (speedup 1.0000x reference)
#include <cuda_runtime.h>
#include <cstdint>
#include <cstddef>

// ECGGraphNetwork fused GCN kernel (fp32, packed f32x2 FFMA).
// B=16384 batch, 12 leads, 512 -> 256 -> 256 -> 128 features,
// A-mix (fixed normalized 12x12 adjacency) + bias + relu between layers,
// mean/max over leads at the end -> (B, 256).
//
// One CTA = 4 batch elements = 48 rows. All layers fused; intermediates in smem.
// Weights streamed via cp.async double-buffered 64-row tiles.

#define THREADS 256
#define TB 4              // batch elements per CTA
#define MROWS 48          // TB * 12
#define F_IN 512
#define HID 256
#define OUTF 128
#define KT 64             // k-tile rows

// smem layout (float offsets)
#define ADJ_OFF 0                 // 144 floats (12x12 A_norm), padded to 256
#define SH_OFF  256               // 48 x 258 layer I/O buffer
#define SHS     258
#define WS_OFF  (256 + MROWS*SHS)             // = 12640 ; two 64x256 weight buffers
#define WBUF    (KT*256)                      // 16384 floats per buffer
#define XS_OFF  (WS_OFF + 2*WBUF)             // = 45408 ; two 48x68 x-tile buffers
#define XSS     68
#define XBUF    (MROWS*XSS)                   // 3264 floats per buffer
#define SMEM_FLOATS (XS_OFF + 2*XBUF)         // 51936
#define SMEM_BYTES (SMEM_FLOATS * 4)          // 207744
#define SC_OFF  WS_OFF            // A-mix scratch aliases weight buffers (dead there)
#define SCS     258

// ---------------- packed f32x2 helpers ----------------
__device__ __forceinline__ unsigned long long pack2(float f) {
    unsigned long long r;
    unsigned u = __float_as_uint(f);
    asm("mov.b64 %0, {%1, %1};" : "=l"(r) : "r"(u));
    return r;
}
__device__ __forceinline__ void ffma2(unsigned long long& d, unsigned long long a,
                                      unsigned long long b) {
    asm("fma.rn.f32x2 %0, %1, %2, %0;" : "+l"(d) : "l"(a), "l"(b));
}

// ---------------- cp.async helpers ----------------
__device__ __forceinline__ void cp_async16(uint32_t dst, const void* src) {
    asm volatile("cp.async.cg.shared.global [%0], [%1], 16;" :: "r"(dst), "l"(src));
}
__device__ __forceinline__ void cp_commit() {
    asm volatile("cp.async.commit_group;");
}
template <int N>
__device__ __forceinline__ void cp_wait() {
    asm volatile("cp.async.wait_group %0;" :: "n"(N));
}

// ---------------- fixed graph constants ----------------
// adjacency bitmasks (bit j set if edge (row, j)), degrees of A_eff = adj + 2I
__device__ __constant__ unsigned int c_rowmask[12] = {
    0x01Eu, 0x03Du, 0x02Bu, 0x007u, 0x003u, 0x006u,
    0x080u, 0x140u, 0x280u, 0x500u, 0xA00u, 0x400u
};
__device__ __constant__ float c_deg[12] = {
    6.f, 7.f, 6.f, 5.f, 4.f, 4.f, 3.f, 4.f, 4.f, 4.f, 4.f, 3.f
};

// ---------------- GEMM inner tile: 64 k-steps, 3 rows x NI float2 cols ----------------
template <int NI>
__device__ __forceinline__ void gemm64(const float* __restrict__ sAv, int AS,
                                       const float* __restrict__ sB, int NB,
                                       unsigned long long (&acc)[3][NI],
                                       int r0, int c0) {
    const float* a0p = sAv + (r0 + 0) * AS;
    const float* a1p = sAv + (r0 + 1) * AS;
    const float* a2p = sAv + (r0 + 2) * AS;
#pragma unroll 4
    for (int k = 0; k < KT; k++) {
        unsigned long long pa0 = pack2(a0p[k]);
        unsigned long long pa1 = pack2(a1p[k]);
        unsigned long long pa2 = pack2(a2p[k]);
        const float* br = sB + k * NB + c0;
#pragma unroll
        for (int i = 0; i < NI; i++) {
            unsigned long long bv =
                *reinterpret_cast<const unsigned long long*>(br + 32 * i);
            ffma2(acc[0][i], pa0, bv);
            ffma2(acc[1][i], pa1, bv);
            ffma2(acc[2][i], pa2, bv);
        }
    }
}

// ---------------- A-mix + bias (+relu) epilogue ----------------
template <int NI, bool RELU>
__device__ __forceinline__ void mix_store(float* __restrict__ sC,
                                          float* __restrict__ sH,
                                          const float* __restrict__ sAdj,
                                          const float* __restrict__ bg,
                                          unsigned long long (&acc)[3][NI],
                                          int r0, int c0) {
    // stage raw C = X*W into scratch
#pragma unroll
    for (int j = 0; j < 3; j++)
#pragma unroll
        for (int i = 0; i < NI; i++)
            *reinterpret_cast<unsigned long long*>(sC + (r0 + j) * SCS + c0 + 32 * i) =
                acc[j][i];
    __syncthreads();

    int base = (r0 / 12) * 12;  // rows r0..r0+2 provably share one 12-group (r0 = 3*tr)
#pragma unroll
    for (int j = 0; j < 3; j++) {
        int l = (r0 + j) - base;
        const float* ar = sAdj + l * 12;
        unsigned long long ap[12];
#pragma unroll
        for (int m = 0; m < 12; m++) ap[m] = pack2(ar[m]);
#pragma unroll
        for (int i = 0; i < NI; i++) {
            unsigned long long y =
                *reinterpret_cast<const unsigned long long*>(bg + c0 + 32 * i);
            const float* cp = sC + base * SCS + c0 + 32 * i;
#pragma unroll
            for (int m = 0; m < 12; m++) {
                unsigned long long cv =
                    *reinterpret_cast<const unsigned long long*>(cp + m * SCS);
                ffma2(y, ap[m], cv);
            }
            if (RELU) {
                float2 u = *reinterpret_cast<float2*>(&y);
                u.x = fmaxf(u.x, 0.0f);
                u.y = fmaxf(u.y, 0.0f);
                y = *reinterpret_cast<unsigned long long*>(&u);
            }
            *reinterpret_cast<unsigned long long*>(sH + (r0 + j) * SHS + c0 + 32 * i) = y;
        }
    }
    __syncthreads();
}

__global__ void __launch_bounds__(THREADS, 1)
ecg_gcn_fused_kernel(const float* __restrict__ x,
                     const float* __restrict__ W1, const float* __restrict__ b1,
                     const float* __restrict__ W2, const float* __restrict__ b2,
                     const float* __restrict__ W3, const float* __restrict__ b3,
                     float* __restrict__ out) {
    extern __shared__ float sm[];
    float* sAdj = sm + ADJ_OFF;
    float* sH   = sm + SH_OFF;
    float* sWs  = sm + WS_OFF;
    float* sXs  = sm + XS_OFF;
    float* sC   = sm + SC_OFF;

    const int tid = threadIdx.x;

    // build normalized adjacency once per CTA
    if (tid < 144) {
        int l = tid / 12, m = tid % 12;
        float ae = (l == m) ? 2.0f : (((c_rowmask[l] >> m) & 1u) ? 1.0f : 0.0f);
        sAdj[tid] = ae / sqrtf(c_deg[l] * c_deg[m]);
    }

    const int tr = tid >> 4;          // 0..15 row-thread
    const int tc = tid & 15;          // 0..15 col-thread
    const int r0 = tr * 3;            // 3 rows per thread
    const int c0 = tc * 2;            // cols c0 + 32*i (+0/1)

    const float* xg = x + (size_t)blockIdx.x * (TB * 12 * F_IN);

    uint32_t xs_u32 = (uint32_t)__cvta_generic_to_shared(sXs);
    uint32_t ws_u32 = (uint32_t)__cvta_generic_to_shared(sWs);

    // x tile loader: 48 rows x 64 floats -> smem stride 68 (16B-aligned rows)
    auto issue_x = [&](int t, int buf) {
        const float* src0 = xg + t * KT;
        uint32_t d0 = xs_u32 + buf * (XBUF * 4);
#pragma unroll
        for (int j = 0; j < 3; j++) {
            int idx = tid + j * 256;
            int row = idx >> 4, c4 = idx & 15;
            cp_async16(d0 + row * (XSS * 4) + c4 * 16, src0 + row * F_IN + c4 * 4);
        }
    };
    // weight tile loader: 64 x NB contiguous rows from Wg
    auto issue_w = [&](const float* Wg, int nb, int t, int buf) {
        const float* src0 = Wg + t * KT * nb;
        uint32_t d0 = ws_u32 + buf * (WBUF * 4);
        int cnt = (KT * nb) / (4 * 256);   // 16 for nb=256, 8 for nb=128
        for (int j = 0; j < cnt; j++) {
            int idx = tid + j * 256;
            cp_async16(d0 + idx * 16, src0 + idx * 4);
        }
    };

    // ================= LAYER 1: (48x512) @ (512x256) =================
    unsigned long long acc1[3][8];
#pragma unroll
    for (int j = 0; j < 3; j++)
#pragma unroll
        for (int i = 0; i < 8; i++) acc1[j][i] = 0ull;

    issue_x(0, 0);
    issue_w(W1, 256, 0, 0);
    cp_commit();
#pragma unroll 1
    for (int t = 0; t < 8; t++) {
        if (t < 7) {
            issue_x(t + 1, (t + 1) & 1);
            issue_w(W1, 256, t + 1, (t + 1) & 1);
            cp_commit();
            cp_wait<1>();
        } else {
            cp_wait<0>();
        }
        __syncthreads();
        gemm64<8>(sXs + (t & 1) * XBUF, XSS, sWs + (t & 1) * WBUF, 256, acc1, r0, c0);
        __syncthreads();
    }
    mix_store<8, true>(sC, sH, sAdj, b1, acc1, r0, c0);

    // ================= LAYER 2: (48x256) @ (256x256) =================
    unsigned long long acc2[3][8];
#pragma unroll
    for (int j = 0; j < 3; j++)
#pragma unroll
        for (int i = 0; i < 8; i++) acc2[j][i] = 0ull;

    issue_w(W2, 256, 0, 0);
    cp_commit();
#pragma unroll 1
    for (int t = 0; t < 4; t++) {
        if (t < 3) {
            issue_w(W2, 256, t + 1, (t + 1) & 1);
            cp_commit();
            cp_wait<1>();
        } else {
            cp_wait<0>();
        }
        __syncthreads();
        gemm64<8>(sH + t * KT, SHS, sWs + (t & 1) * WBUF, 256, acc2, r0, c0);
        __syncthreads();
    }
    mix_store<8, true>(sC, sH, sAdj, b2, acc2, r0, c0);

    // ================= LAYER 3: (48x256) @ (256x128) =================
    unsigned long long acc3[3][4];
#pragma unroll
    for (int j = 0; j < 3; j++)
#pragma unroll
        for (int i = 0; i < 4; i++) acc3[j][i] = 0ull;

    issue_w(W3, 128, 0, 0);
    cp_commit();
#pragma unroll 1
    for (int t = 0; t < 4; t++) {
        if (t < 3) {
            issue_w(W3, 128, t + 1, (t + 1) & 1);
            cp_commit();
            cp_wait<1>();
        } else {
            cp_wait<0>();
        }
        __syncthreads();
        gemm64<4>(sH + t * KT, SHS, sWs + (t & 1) * WBUF, 128, acc3, r0, c0);
        __syncthreads();
    }
    mix_store<4, false>(sC, sH, sAdj, b3, acc3, r0, c0);

    // ================= mean / max over leads -> out (B, 256) =================
#pragma unroll 1
    for (int idx = tid; idx < TB * 128; idx += THREADS) {
        int bi = idx >> 7;
        int c = idx & 127;
        const float* hp = sH + (bi * 12) * SHS + c;
        float s = 0.0f, mx = -3.402823466e38f;
#pragma unroll
        for (int l = 0; l < 12; l++) {
            float v = hp[l * SHS];
            s += v;
            mx = fmaxf(mx, v);
        }
        size_t ob = ((size_t)blockIdx.x * TB + bi) * 256;
        out[ob + c] = s * (1.0f / 12.0f);
        out[ob + 128 + c] = mx;
    }
}

extern "C" void kernel_launch(void* const* d_in, const int* in_sizes, int n_in,
                              void* d_out, int out_size) {
    const float* x  = (const float*)d_in[0];
    const float* W1 = (const float*)d_in[1];
    const float* b1 = (const float*)d_in[2];
    const float* W2 = (const float*)d_in[3];
    const float* b2 = (const float*)d_in[4];
    const float* W3 = (const float*)d_in[5];
    const float* b3 = (const float*)d_in[6];
    float* out = (float*)d_out;

    int B = in_sizes[0] / (12 * F_IN);   // 16384
    int grid = B / TB;                   // 4096

    cudaFuncSetAttribute(ecg_gcn_fused_kernel,
                         cudaFuncAttributeMaxDynamicSharedMemorySize, SMEM_BYTES);
    ecg_gcn_fused_kernel<<<grid, THREADS, SMEM_BYTES>>>(x, W1, b1, W2, b2, W3, b3, out);
}

// round 4
// speedup vs baseline: 1.2288x; 1.2288x over previous
#include <cuda_runtime.h>
#include <cstdint>
#include <cstddef>

// ECGGraphNetwork fused GCN kernel (fp32, packed f32x2 FFMA), v2.
// Thread tile raised to 6 rows x NI float2 cols (8x32 thread grid) to halve
// shared-memory B traffic per FMA; A-operand loads vectorized (LDS.128 over
// 4 k-steps, warp-uniform broadcast). Flips kernel from smem-bound to
// FMA-issue-bound.

#define THREADS 256
#define TB 4              // batch elements per CTA
#define MROWS 48          // TB * 12
#define F_IN 512
#define KT 64             // k-tile rows

typedef unsigned long long ULL;

// smem layout (float offsets)
#define ADJ_OFF 0                 // 144 floats (12x12 A_norm), padded to 256
#define SH_OFF  256               // 48 x 260 layer I/O buffer (16B-aligned rows)
#define SHS     260
#define WS_OFF  (256 + MROWS*SHS)             // two 64x256 weight buffers
#define WBUF    (KT*256)                      // 16384 floats per buffer
#define XS_OFF  (WS_OFF + 2*WBUF)             // two 48x68 x-tile buffers
#define XSS     68
#define XBUF    (MROWS*XSS)
#define SMEM_FLOATS (XS_OFF + 2*XBUF)
#define SMEM_BYTES (SMEM_FLOATS * 4)          // 208128
#define SC_OFF  WS_OFF            // A-mix scratch aliases weight buffers
#define SCS     258

// ---------------- packed f32x2 helpers ----------------
__device__ __forceinline__ ULL pack2(float f) {
    ULL r;
    unsigned u = __float_as_uint(f);
    asm("mov.b64 %0, {%1, %1};" : "=l"(r) : "r"(u));
    return r;
}
__device__ __forceinline__ void ffma2(ULL& d, ULL a, ULL b) {
    asm("fma.rn.f32x2 %0, %1, %2, %0;" : "+l"(d) : "l"(a), "l"(b));
}

// ---------------- cp.async helpers ----------------
__device__ __forceinline__ void cp_async16(uint32_t dst, const void* src) {
    asm volatile("cp.async.cg.shared.global [%0], [%1], 16;" :: "r"(dst), "l"(src));
}
__device__ __forceinline__ void cp_commit() {
    asm volatile("cp.async.commit_group;");
}
template <int N>
__device__ __forceinline__ void cp_wait() {
    asm volatile("cp.async.wait_group %0;" :: "n"(N));
}

// ---------------- fixed graph constants ----------------
__device__ __constant__ unsigned int c_rowmask[12] = {
    0x01Eu, 0x03Du, 0x02Bu, 0x007u, 0x003u, 0x006u,
    0x080u, 0x140u, 0x280u, 0x500u, 0xA00u, 0x400u
};
__device__ __constant__ float c_deg[12] = {
    6.f, 7.f, 6.f, 5.f, 4.f, 4.f, 3.f, 4.f, 4.f, 4.f, 4.f, 3.f
};

// ---------------- GEMM inner tile: 64 k-steps, 6 rows x NI float2 cols ----------------
// Col offsets: c0 + 64*i (interleaved) -> conflict-free LDS.64 across the warp.
// A rows: warp-uniform (tr = tid>>5), loaded as float4 per 4 k-steps (broadcast).
template <int NI>
__device__ __forceinline__ void gemm64(const float* __restrict__ sA, int AS,
                                       const float* __restrict__ sB, int NB,
                                       ULL (&acc)[6][NI], int r0, int c0) {
#pragma unroll 2
    for (int k4 = 0; k4 < KT; k4 += 4) {
        float4 av[6];
#pragma unroll
        for (int j = 0; j < 6; j++)
            av[j] = *reinterpret_cast<const float4*>(sA + (r0 + j) * AS + k4);
#pragma unroll
        for (int kk = 0; kk < 4; kk++) {
            ULL pb[NI];
            const float* br = sB + (k4 + kk) * NB + c0;
#pragma unroll
            for (int i = 0; i < NI; i++)
                pb[i] = *reinterpret_cast<const ULL*>(br + 64 * i);
#pragma unroll
            for (int j = 0; j < 6; j++) {
                ULL pa = pack2(reinterpret_cast<const float*>(&av[j])[kk]);
#pragma unroll
                for (int i = 0; i < NI; i++) ffma2(acc[j][i], pa, pb[i]);
            }
        }
    }
}

// ---------------- A-mix + bias (+relu) epilogue ----------------
template <int NI, bool RELU>
__device__ __forceinline__ void mix_store(float* __restrict__ sC,
                                          float* __restrict__ sH,
                                          const float* __restrict__ sAdj,
                                          const float* __restrict__ bg,
                                          ULL (&acc)[6][NI],
                                          int r0, int c0) {
    // stage raw C = X*W into scratch
#pragma unroll
    for (int j = 0; j < 6; j++)
#pragma unroll
        for (int i = 0; i < NI; i++)
            *reinterpret_cast<ULL*>(sC + (r0 + j) * SCS + c0 + 64 * i) = acc[j][i];
    __syncthreads();

    int base = (r0 / 12) * 12;  // rows r0..r0+5 share one 12-group (6 | 12)
#pragma unroll
    for (int j = 0; j < 6; j++) {
        int l = (r0 + j) - base;
        const float* ar = sAdj + l * 12;
        ULL ap[12];
#pragma unroll
        for (int m = 0; m < 12; m++) ap[m] = pack2(ar[m]);
#pragma unroll
        for (int i = 0; i < NI; i++) {
            ULL y = *reinterpret_cast<const ULL*>(bg + c0 + 64 * i);
            const float* cp = sC + base * SCS + c0 + 64 * i;
#pragma unroll
            for (int m = 0; m < 12; m++) {
                ULL cv = *reinterpret_cast<const ULL*>(cp + m * SCS);
                ffma2(y, ap[m], cv);
            }
            if (RELU) {
                float2 u = *reinterpret_cast<float2*>(&y);
                u.x = fmaxf(u.x, 0.0f);
                u.y = fmaxf(u.y, 0.0f);
                y = *reinterpret_cast<ULL*>(&u);
            }
            *reinterpret_cast<ULL*>(sH + (r0 + j) * SHS + c0 + 64 * i) = y;
        }
    }
    __syncthreads();
}

__global__ void __launch_bounds__(THREADS, 1)
ecg_gcn_fused_kernel(const float* __restrict__ x,
                     const float* __restrict__ W1, const float* __restrict__ b1,
                     const float* __restrict__ W2, const float* __restrict__ b2,
                     const float* __restrict__ W3, const float* __restrict__ b3,
                     float* __restrict__ out) {
    extern __shared__ float sm[];
    float* sAdj = sm + ADJ_OFF;
    float* sH   = sm + SH_OFF;
    float* sWs  = sm + WS_OFF;
    float* sXs  = sm + XS_OFF;
    float* sC   = sm + SC_OFF;

    const int tid = threadIdx.x;

    // build normalized adjacency once per CTA
    if (tid < 144) {
        int l = tid / 12, m = tid % 12;
        float ae = (l == m) ? 2.0f : (((c_rowmask[l] >> m) & 1u) ? 1.0f : 0.0f);
        sAdj[tid] = ae / sqrtf(c_deg[l] * c_deg[m]);
    }

    const int tr = tid >> 5;          // 0..7 row-thread (warp-uniform)
    const int tc = tid & 31;          // 0..31 col-thread
    const int r0 = tr * 6;            // 6 rows per thread
    const int c0 = tc * 2;            // cols c0 + 64*i (+0/1)

    const float* xg = x + (size_t)blockIdx.x * (TB * 12 * F_IN);

    uint32_t xs_u32 = (uint32_t)__cvta_generic_to_shared(sXs);
    uint32_t ws_u32 = (uint32_t)__cvta_generic_to_shared(sWs);

    // x tile loader: 48 rows x 64 floats -> smem stride 68 (16B-aligned rows)
    auto issue_x = [&](int t, int buf) {
        const float* src0 = xg + t * KT;
        uint32_t d0 = xs_u32 + buf * (XBUF * 4);
#pragma unroll
        for (int j = 0; j < 3; j++) {
            int idx = tid + j * 256;
            int row = idx >> 4, c4 = idx & 15;
            cp_async16(d0 + row * (XSS * 4) + c4 * 16, src0 + row * F_IN + c4 * 4);
        }
    };
    // weight tile loader: 64 x NB contiguous rows from Wg
    auto issue_w = [&](const float* Wg, int nb, int t, int buf) {
        const float* src0 = Wg + t * KT * nb;
        uint32_t d0 = ws_u32 + buf * (WBUF * 4);
        int cnt = (KT * nb) / (4 * 256);   // 16 for nb=256, 8 for nb=128
        for (int j = 0; j < cnt; j++) {
            int idx = tid + j * 256;
            cp_async16(d0 + idx * 16, src0 + idx * 4);
        }
    };

    // ================= LAYER 1: (48x512) @ (512x256) =================
    ULL acc1[6][4];
#pragma unroll
    for (int j = 0; j < 6; j++)
#pragma unroll
        for (int i = 0; i < 4; i++) acc1[j][i] = 0ull;

    issue_x(0, 0);
    issue_w(W1, 256, 0, 0);
    cp_commit();
#pragma unroll 1
    for (int t = 0; t < 8; t++) {
        if (t < 7) {
            issue_x(t + 1, (t + 1) & 1);
            issue_w(W1, 256, t + 1, (t + 1) & 1);
            cp_commit();
            cp_wait<1>();
        } else {
            cp_wait<0>();
        }
        __syncthreads();
        gemm64<4>(sXs + (t & 1) * XBUF, XSS, sWs + (t & 1) * WBUF, 256, acc1, r0, c0);
        __syncthreads();
    }
    mix_store<4, true>(sC, sH, sAdj, b1, acc1, r0, c0);

    // ================= LAYER 2: (48x256) @ (256x256) =================
    ULL acc2[6][4];
#pragma unroll
    for (int j = 0; j < 6; j++)
#pragma unroll
        for (int i = 0; i < 4; i++) acc2[j][i] = 0ull;

    issue_w(W2, 256, 0, 0);
    cp_commit();
#pragma unroll 1
    for (int t = 0; t < 4; t++) {
        if (t < 3) {
            issue_w(W2, 256, t + 1, (t + 1) & 1);
            cp_commit();
            cp_wait<1>();
        } else {
            cp_wait<0>();
        }
        __syncthreads();
        gemm64<4>(sH + t * KT, SHS, sWs + (t & 1) * WBUF, 256, acc2, r0, c0);
        __syncthreads();
    }
    mix_store<4, true>(sC, sH, sAdj, b2, acc2, r0, c0);

    // ================= LAYER 3: (48x256) @ (256x128) =================
    ULL acc3[6][2];
#pragma unroll
    for (int j = 0; j < 6; j++)
#pragma unroll
        for (int i = 0; i < 2; i++) acc3[j][i] = 0ull;

    issue_w(W3, 128, 0, 0);
    cp_commit();
#pragma unroll 1
    for (int t = 0; t < 4; t++) {
        if (t < 3) {
            issue_w(W3, 128, t + 1, (t + 1) & 1);
            cp_commit();
            cp_wait<1>();
        } else {
            cp_wait<0>();
        }
        __syncthreads();
        gemm64<2>(sH + t * KT, SHS, sWs + (t & 1) * WBUF, 128, acc3, r0, c0);
        __syncthreads();
    }
    mix_store<2, false>(sC, sH, sAdj, b3, acc3, r0, c0);

    // ================= mean / max over leads -> out (B, 256) =================
#pragma unroll 1
    for (int idx = tid; idx < TB * 128; idx += THREADS) {
        int bi = idx >> 7;
        int c = idx & 127;
        const float* hp = sH + (bi * 12) * SHS + c;
        float s = 0.0f, mx = -3.402823466e38f;
#pragma unroll
        for (int l = 0; l < 12; l++) {
            float v = hp[l * SHS];
            s += v;
            mx = fmaxf(mx, v);
        }
        size_t ob = ((size_t)blockIdx.x * TB + bi) * 256;
        out[ob + c] = s * (1.0f / 12.0f);
        out[ob + 128 + c] = mx;
    }
}

extern "C" void kernel_launch(void* const* d_in, const int* in_sizes, int n_in,
                              void* d_out, int out_size) {
    const float* x  = (const float*)d_in[0];
    const float* W1 = (const float*)d_in[1];
    const float* b1 = (const float*)d_in[2];
    const float* W2 = (const float*)d_in[3];
    const float* b2 = (const float*)d_in[4];
    const float* W3 = (const float*)d_in[5];
    const float* b3 = (const float*)d_in[6];
    float* out = (float*)d_out;

    int B = in_sizes[0] / (12 * F_IN);   // 16384
    int grid = B / TB;                   // 4096

    cudaFuncSetAttribute(ecg_gcn_fused_kernel,
                         cudaFuncAttributeMaxDynamicSharedMemorySize, SMEM_BYTES);
    ecg_gcn_fused_kernel<<<grid, THREADS, SMEM_BYTES>>>(x, W1, b1, W2, b2, W3, b3, out);
}